// round 1
// baseline (speedup 1.0000x reference)
#include <cuda_runtime.h>
#include <math.h>

// ---------------------------------------------------------------------------
// 2-layer LSTM, T=512, B=64, H=512, fp32.
// Persistent kernel: 128 CTAs x 256 threads, all co-resident (1 CTA/SM,
// 144KB smem each, GB300 has 148+ SMs). CTA j owns hidden columns
// [4j, 4j+4) and the 16 gate rows {g*512 + 4j + cc} of BOTH layers; the
// corresponding weight slices of Wxh0/Whh0/Wxh1/Whh1 are loaded into smem
// once and reused for all 512 timesteps. Grid barrier (sense-reversing,
// L2 atomics + __threadfence for release/acquire + L1 invalidate) twice per
// timestep. h0/h1 ping-pong buffers in __device__ globals.
// ---------------------------------------------------------------------------

#define T_LEN 512
#define BSZ   64
#define HID   512
#define NCTA  128
#define NTHR  256

// 16 weight rows per CTA, K=512, padded row stride 513 (bank-conflict-free)
#define WPAD  513
// A-tile: 32 k x 64 b, padded row stride 68 (16B-aligned rows, low conflicts)
#define APAD  68

#define SMEM_FLOATS (4 * 16 * WPAD + 32 * APAD + 1024 + 32)
#define SMEM_BYTES  (SMEM_FLOATS * 4)

// state buffers (persistent across kernel, re-zeroed each launch)
__device__ float g_h0[2][BSZ * HID];
__device__ float g_h1[2][BSZ * HID];
__device__ float g_c0[BSZ * HID];
__device__ float g_c1[BSZ * HID];
__device__ unsigned g_cnt;   // zero-init, returns to zero after each barrier
__device__ unsigned g_gen;   // monotonically increasing across launches (ok)

__device__ __forceinline__ float sigm(float x) { return 1.0f / (1.0f + expf(-x)); }

// Grid-wide barrier. All 128 CTAs are co-resident by construction.
// __threadfence before arrive = release (stores visible at GPU scope);
// __threadfence after observing release = acquire + L1D invalidate (CCTL.IVALL).
__device__ __forceinline__ void grid_bar() {
    __threadfence();
    __syncthreads();
    if (threadIdx.x == 0) {
        volatile unsigned* vg = &g_gen;
        unsigned g = *vg;
        unsigned t = atomicAdd(&g_cnt, 1u);
        if (t == NCTA - 1) {
            atomicExch(&g_cnt, 0u);
            __threadfence();
            atomicAdd(&g_gen, 1u);
        } else {
            while (*vg == g) { }
        }
        __threadfence();
    }
    __syncthreads();
}

// acc[0..3] += A[b, :] . Wrow over K=512, for 4 batch rows (bq4..bq4+3),
// one gate row c. A is [64][512] row-major in gmem. As is the shared
// staging tile [32][APAD], Ws is the CTA's weight slice [16][WPAD].
__device__ __forceinline__ void gemm_acc(
    const float* __restrict__ A, const float* __restrict__ Ws,
    float* __restrict__ As, int tid, int bq4, int c, float acc[4])
{
    for (int ks = 0; ks < 512; ks += 32) {
        __syncthreads();   // previous tile fully consumed
        // stage 64x32 A-tile, transposed to [k][b]
#pragma unroll
        for (int i = 0; i < 2; i++) {
            int idx = tid + i * NTHR;       // 0..511 float4 units
            int b   = idx >> 3;             // 0..63
            int kq  = idx & 7;              // 0..7
            float4 v = *reinterpret_cast<const float4*>(A + b * 512 + ks + (kq << 2));
            float* d = As + (kq << 2) * APAD + b;
            d[0 * APAD] = v.x; d[1 * APAD] = v.y; d[2 * APAD] = v.z; d[3 * APAD] = v.w;
        }
        __syncthreads();
        const float* wrow = Ws + c * WPAD + ks;
#pragma unroll
        for (int kk = 0; kk < 32; kk++) {
            float4 a = *reinterpret_cast<const float4*>(As + kk * APAD + bq4);
            float  w = wrow[kk];
            acc[0] = fmaf(a.x, w, acc[0]);
            acc[1] = fmaf(a.y, w, acc[1]);
            acc[2] = fmaf(a.z, w, acc[2]);
            acc[3] = fmaf(a.w, w, acc[3]);
        }
    }
}

__global__ void __launch_bounds__(NTHR, 1) lstm_persistent(
    const float* __restrict__ x,    // [T, B, H]
    const float* __restrict__ Wxh,  // [2, 2048, 512]
    const float* __restrict__ Whh,  // [2, 2048, 512]
    const float* __restrict__ bxh,  // [2, 2048]
    const float* __restrict__ bhh,  // [2, 2048]
    float* __restrict__ out)        // [T*B*H] ++ hT[2,B,H] ++ cT[2,B,H]
{
    extern __shared__ float sm[];
    const int tid = threadIdx.x;
    const int bj  = blockIdx.x;           // 0..127, hidden cols [4bj, 4bj+4)

    float* W0x  = sm;
    float* W0h  = W0x + 16 * WPAD;
    float* W1x  = W0h + 16 * WPAD;
    float* W1h  = W1x + 16 * WPAD;
    float* As   = W1h + 16 * WPAD;        // 32 * APAD
    float* gbuf = As + 32 * APAD;         // [16 bq][16 c][4 u]
    float* bs   = gbuf + 1024;            // 16 L0 biases + 16 L1 biases

    // ---- prologue: load weight slices to smem, sum biases, zero state ----
    for (int idx = tid; idx < 16 * 512; idx += NTHR) {
        int r = idx >> 9, k = idx & 511;                 // r: 0..15 (= g*4+cc)
        int n = ((r >> 2) << 9) + (bj << 2) + (r & 3);   // gate row in [0,2048)
        size_t o0 = (size_t)n * 512 + k;
        size_t o1 = (size_t)(2048 + n) * 512 + k;
        W0x[r * WPAD + k] = Wxh[o0];
        W0h[r * WPAD + k] = Whh[o0];
        W1x[r * WPAD + k] = Wxh[o1];
        W1h[r * WPAD + k] = Whh[o1];
    }
    if (tid < 16) {
        int n = ((tid >> 2) << 9) + (bj << 2) + (tid & 3);
        bs[tid]      = bxh[n] + bhh[n];
        bs[16 + tid] = bxh[2048 + n] + bhh[2048 + n];
    }
    {
        int i = bj * NTHR + tid;   // covers [0, 32768) exactly
        g_h0[0][i] = 0.f; g_h0[1][i] = 0.f;
        g_h1[0][i] = 0.f; g_h1[1][i] = 0.f;
        g_c0[i]    = 0.f; g_c1[i]    = 0.f;
    }
    grid_bar();

    const int c    = tid & 15;          // gate row within CTA (g = c>>2, cc = c&3)
    const int bq4  = (tid >> 4) << 2;   // base batch row for gemm (4 rows)
    const int ub   = tid >> 2;          // batch row for the c/h update
    const int ucc  = tid & 3;           // hidden col offset for the update
    const int hcol = bj << 2;
    const int si   = ub * HID + hcol + ucc;  // state index this thread updates
    const int gb   = ((ub >> 2) * 16) * 4 + (ub & 3);  // gbuf base for update reads

    for (int t = 0; t < T_LEN; t++) {
        const int p = t & 1;

        // ================= layer 0 =================
        {
            float b0 = bs[c];
            float acc[4] = {b0, b0, b0, b0};
            gemm_acc(x + (size_t)t * (BSZ * HID), W0x, As, tid, bq4, c, acc);
            gemm_acc(g_h0[p],                     W0h, As, tid, bq4, c, acc);

            float* gd = gbuf + ((tid >> 4) * 16 + c) * 4;
            gd[0] = acc[0]; gd[1] = acc[1]; gd[2] = acc[2]; gd[3] = acc[3];
            __syncthreads();

            float ig = gbuf[gb + (0 * 4 + ucc) * 4];
            float fg = gbuf[gb + (1 * 4 + ucc) * 4];
            float gg = gbuf[gb + (2 * 4 + ucc) * 4];
            float og = gbuf[gb + (3 * 4 + ucc) * 4];
            float cp = g_c0[si];
            float cn = sigm(fg) * cp + sigm(ig) * tanhf(gg);
            float hn = sigm(og) * tanhf(cn);
            g_c0[si] = cn;
            g_h0[1 - p][si] = hn;
        }
        grid_bar();

        // ================= layer 1 =================
        {
            float b1 = bs[16 + c];
            float acc[4] = {b1, b1, b1, b1};
            gemm_acc(g_h0[1 - p], W1x, As, tid, bq4, c, acc);  // input = new h0
            gemm_acc(g_h1[p],     W1h, As, tid, bq4, c, acc);

            float* gd = gbuf + ((tid >> 4) * 16 + c) * 4;
            gd[0] = acc[0]; gd[1] = acc[1]; gd[2] = acc[2]; gd[3] = acc[3];
            __syncthreads();

            float ig = gbuf[gb + (0 * 4 + ucc) * 4];
            float fg = gbuf[gb + (1 * 4 + ucc) * 4];
            float gg = gbuf[gb + (2 * 4 + ucc) * 4];
            float og = gbuf[gb + (3 * 4 + ucc) * 4];
            float cp = g_c1[si];
            float cn = sigm(fg) * cp + sigm(ig) * tanhf(gg);
            float hn = sigm(og) * tanhf(cn);
            g_c1[si] = cn;
            g_h1[1 - p][si] = hn;
            out[(size_t)t * (BSZ * HID) + si] = hn;   // top-layer hidden
        }
        grid_bar();
    }

    // ---- epilogue: (hT, cT). T even -> final states live in buffer 0. ----
    {
        int i = bj * NTHR + tid;                 // [0, 32768)
        const size_t OFF = (size_t)T_LEN * BSZ * HID;
        out[OFF +             i] = g_h0[0][i];   // hT layer 0
        out[OFF + 1 * 32768 + i] = g_h1[0][i];   // hT layer 1
        out[OFF + 2 * 32768 + i] = g_c0[i];      // cT layer 0
        out[OFF + 3 * 32768 + i] = g_c1[i];      // cT layer 1
    }
}

extern "C" void kernel_launch(void* const* d_in, const int* in_sizes, int n_in,
                              void* d_out, int out_size) {
    const float* x   = (const float*)d_in[0];
    const float* Wxh = (const float*)d_in[1];
    const float* Whh = (const float*)d_in[2];
    const float* bxh = (const float*)d_in[3];
    const float* bhh = (const float*)d_in[4];
    float* out = (float*)d_out;

    cudaFuncSetAttribute(lstm_persistent,
                         cudaFuncAttributeMaxDynamicSharedMemorySize, SMEM_BYTES);
    lstm_persistent<<<NCTA, NTHR, SMEM_BYTES>>>(x, Wxh, Whh, bxh, bhh, out);
}

// round 2
// speedup vs baseline: 2.7440x; 2.7440x over previous
#include <cuda_runtime.h>
#include <math.h>
#include <stdint.h>

// ---------------------------------------------------------------------------
// 2-layer LSTM, T=512, B=64, H=512, fp32.
// Persistent kernel, 128 CTAs x 256 threads (1 CTA/SM, all co-resident).
// CTA j owns hidden cols [4j,4j+4) => 16 gate rows per layer; weight slices
// live TRANSPOSED [k][c] in smem for the whole run. Per step, per layer:
// register-tiled GEMM (4 gate-rows x 4 batches per thread, K split 4 ways),
// packed fma.rn.f32x2 math, cp.async double-buffered A tiles (A kept in
// [k][b] layout: x pre-transposed once; h ping-pong buffers stored
// transposed). Cell state c lives in registers. 2 grid barriers / step.
// ---------------------------------------------------------------------------

#define T_LEN 512
#define BSZ   64
#define HID   512
#define NCTA  128
#define NTHR  256

// smem layout (in floats)
#define WT_MAT_STRIDE (512*16)                 // one transposed weight mat [512][16]
#define AB_OFF        (4*WT_MAT_STRIDE)        // 32768
#define ABUF_STRIDE   (32*68)                  // one A tile [32][68]
#define GB_OFF        (AB_OFF + 8*ABUF_STRIDE) // 32768 + 17408 = 50176
#define GB_KT_STRIDE  (16*68)                  // 1088
#define BS_OFF        (GB_OFF + 4*GB_KT_STRIDE)// 54528
#define SMEM_FLOATS   (BS_OFF + 32)
#define SMEM_BYTES    (SMEM_FLOATS * 4)        // 218368 B  (< 227KB cap)

// persistent scratch ([t][k][b] / [k][b] layouts)
__device__ float g_xT [T_LEN][HID][BSZ];   // 64 MB, x transposed per step
__device__ float g_h0T[2][HID][BSZ];
__device__ float g_h1T[2][HID][BSZ];
__device__ unsigned g_cnt;   // returns to 0 after every barrier
__device__ unsigned g_gen;   // monotonic across launches (ok)

__device__ __forceinline__ float sigm(float x) { return 1.0f / (1.0f + expf(-x)); }

__device__ __forceinline__ unsigned long long pack2(float x) {
    unsigned long long d;
    asm("mov.b64 %0, {%1, %1};" : "=l"(d) : "f"(x));
    return d;
}
__device__ __forceinline__ unsigned long long ffma2(
    unsigned long long a, unsigned long long b, unsigned long long c) {
    unsigned long long d;
    asm("fma.rn.f32x2 %0, %1, %2, %3;" : "=l"(d) : "l"(a), "l"(b), "l"(c));
    return d;
}
__device__ __forceinline__ void cp16(float* dst, const float* src) {
    unsigned s = (unsigned)__cvta_generic_to_shared(dst);
    asm volatile("cp.async.cg.shared.global [%0], [%1], 16;" :: "r"(s), "l"(src));
}

// Grid-wide barrier (proven in round 1). All 128 CTAs co-resident.
__device__ __forceinline__ void grid_bar() {
    __threadfence();
    __syncthreads();
    if (threadIdx.x == 0) {
        volatile unsigned* vg = &g_gen;
        unsigned g = *vg;
        unsigned t = atomicAdd(&g_cnt, 1u);
        if (t == NCTA - 1) {
            atomicExch(&g_cnt, 0u);
            __threadfence();
            atomicAdd(&g_gen, 1u);
        } else {
            while (*vg == g) { }
        }
        __threadfence();
    }
    __syncthreads();
}

// One layer's GEMM: gates(partial) = A0 . Wx^T + A1 . Wh^T for this CTA's
// 16 gate rows. A0/A1 are [512][64] ([k][b]) in gmem. Team kt covers
// k in [kt*128, kt*128+128) of each mat (8 tiles of 32k total), double
// buffered via cp.async; partials go to gbuf[kt][c][b].
__device__ __forceinline__ void gemm_layer(
    float* sm, int wbase, const float* A0, const float* A1,
    int kt, int cq, int bq, int r)
{
    unsigned long long acc[4][2] = {};
    float* Ab0 = sm + AB_OFF + (kt*2    ) * ABUF_STRIDE;
    float* Ab1 = sm + AB_OFF + (kt*2 + 1) * ABUF_STRIDE;

    // prefetch tile 0
    {
        const float* src = A0 + (kt*128)*64;
        #pragma unroll
        for (int j = 0; j < 8; j++) {
            int idx = r + j*64; int kk = idx >> 4; int b4 = (idx & 15) << 2;
            cp16(Ab0 + kk*68 + b4, src + kk*64 + b4);
        }
        asm volatile("cp.async.commit_group;" ::: "memory");
    }
    int buf = 0;
    for (int i = 0; i < 8; i++) {
        // all team threads done with the buffer we're about to overwrite
        asm volatile("bar.sync %0, 64;" :: "r"(kt + 1) : "memory");
        if (i < 7) {
            const float* Anext = ((i + 1) < 4) ? A0 : A1;
            const float* src = Anext + (kt*128 + ((i + 1) & 3)*32)*64;
            float* dst = buf ? Ab0 : Ab1;
            #pragma unroll
            for (int j = 0; j < 8; j++) {
                int idx = r + j*64; int kk = idx >> 4; int b4 = (idx & 15) << 2;
                cp16(dst + kk*68 + b4, src + kk*64 + b4);
            }
            asm volatile("cp.async.commit_group;" ::: "memory");
            asm volatile("cp.async.wait_group 1;" ::: "memory");
        } else {
            asm volatile("cp.async.wait_group 0;" ::: "memory");
        }
        asm volatile("bar.sync %0, 64;" :: "r"(kt + 1) : "memory");

        const float* wp = sm + (wbase + (i >> 2))*WT_MAT_STRIDE
                             + (kt*128 + (i & 3)*32)*16 + cq*4;
        const float* ap = (buf ? Ab1 : Ab0) + (bq << 2);
        #pragma unroll
        for (int kk = 0; kk < 32; kk++) {
            float4 w = *reinterpret_cast<const float4*>(wp + kk*16);
            ulonglong2 av = *reinterpret_cast<const ulonglong2*>(ap + kk*68);
            unsigned long long w0 = pack2(w.x), w1 = pack2(w.y),
                               w2 = pack2(w.z), w3 = pack2(w.w);
            acc[0][0] = ffma2(av.x, w0, acc[0][0]);
            acc[0][1] = ffma2(av.y, w0, acc[0][1]);
            acc[1][0] = ffma2(av.x, w1, acc[1][0]);
            acc[1][1] = ffma2(av.y, w1, acc[1][1]);
            acc[2][0] = ffma2(av.x, w2, acc[2][0]);
            acc[2][1] = ffma2(av.y, w2, acc[2][1]);
            acc[3][0] = ffma2(av.x, w3, acc[3][0]);
            acc[3][1] = ffma2(av.y, w3, acc[3][1]);
        }
        buf ^= 1;
    }
    // store K-split partials: gbuf[kt][cq*4+ci][bq*4 .. +3]
    float* gb = sm + GB_OFF + (kt*16 + cq*4)*68 + (bq << 2);
    #pragma unroll
    for (int ci = 0; ci < 4; ci++)
        *reinterpret_cast<ulonglong2*>(gb + ci*68) =
            make_ulonglong2(acc[ci][0], acc[ci][1]);
}

__global__ void transpose_x(const float* __restrict__ x) {
    __shared__ float tile[32][33];
    int t  = blockIdx.z;
    int k0 = blockIdx.x << 5, b0 = blockIdx.y << 5;
    const float* src = x + ((size_t)t*BSZ + b0)*HID + k0;
    #pragma unroll
    for (int i = threadIdx.y; i < 32; i += 8)
        tile[i][threadIdx.x] = src[(size_t)i*HID + threadIdx.x];
    __syncthreads();
    #pragma unroll
    for (int i = threadIdx.y; i < 32; i += 8)
        g_xT[t][k0 + i][b0 + threadIdx.x] = tile[threadIdx.x][i];
}

__global__ void __launch_bounds__(NTHR, 1) lstm_persistent(
    const float* __restrict__ Wxh,  // [2, 2048, 512]
    const float* __restrict__ Whh,  // [2, 2048, 512]
    const float* __restrict__ bxh,  // [2, 2048]
    const float* __restrict__ bhh,  // [2, 2048]
    float* __restrict__ out)        // [T*B*H] ++ hT[2,B,H] ++ cT[2,B,H]
{
    extern __shared__ float sm[];
    const int tid = threadIdx.x;
    const int bj  = blockIdx.x;

    // ---- prologue: weights -> smem TRANSPOSED [k][c]; biases; zero h ----
    for (int idx4 = tid; idx4 < 8192; idx4 += NTHR) {   // float4 units
        int m = idx4 >> 11, rem = idx4 & 2047;
        int c = rem >> 7, k4 = (rem & 127) << 2;
        int layer = m >> 1;
        const float* base = (m & 1) ? Whh : Wxh;
        const float* src = base + ((size_t)layer*2048
                         + (size_t)(c >> 2)*512 + (bj << 2) + (c & 3))*512 + k4;
        float4 v = *reinterpret_cast<const float4*>(src);
        float* d = sm + m*WT_MAT_STRIDE + k4*16 + c;
        d[0] = v.x; d[16] = v.y; d[32] = v.z; d[48] = v.w;
    }
    if (tid < 32) {
        int l = tid >> 4, j = tid & 15;
        int n = (j >> 2)*512 + (bj << 2) + (j & 3);
        sm[BS_OFF + tid] = bxh[l*2048 + n] + bhh[l*2048 + n];
    }
    {
        float* h0z = &g_h0T[0][0][0];
        float* h1z = &g_h1T[0][0][0];
        for (int i = tid; i < 512; i += NTHR) {
            h0z[bj*512 + i] = 0.f;
            h1z[bj*512 + i] = 0.f;
        }
    }
    grid_bar();

    const int kt = tid >> 6, r = tid & 63;   // gemm role
    const int cq = r >> 4,  bq = r & 15;
    const int ub = tid >> 2, ucc = tid & 3;  // update role
    const int col = (bj << 2) + ucc;
    const float* bs = sm + BS_OFF;
    float c0r = 0.f, c1r = 0.f;

    for (int t = 0; t < T_LEN; t++) {
        const int p = t & 1;

        // ================= layer 0 =================
        gemm_layer(sm, 0, &g_xT[t][0][0], &g_h0T[p][0][0], kt, cq, bq, r);
        __syncthreads();
        {
            float gate[4];
            #pragma unroll
            for (int g = 0; g < 4; g++) {
                const float* q = sm + GB_OFF + (g*4 + ucc)*68 + ub;
                gate[g] = q[0] + q[GB_KT_STRIDE] + q[2*GB_KT_STRIDE]
                        + q[3*GB_KT_STRIDE] + bs[g*4 + ucc];
            }
            float ig = sigm(gate[0]), fg = sigm(gate[1]);
            float gg = tanhf(gate[2]), og = sigm(gate[3]);
            c0r = fg*c0r + ig*gg;
            g_h0T[1 - p][col][ub] = og * tanhf(c0r);
        }
        grid_bar();

        // ================= layer 1 =================
        gemm_layer(sm, 2, &g_h0T[1 - p][0][0], &g_h1T[p][0][0], kt, cq, bq, r);
        __syncthreads();
        {
            float gate[4];
            #pragma unroll
            for (int g = 0; g < 4; g++) {
                const float* q = sm + GB_OFF + (g*4 + ucc)*68 + ub;
                gate[g] = q[0] + q[GB_KT_STRIDE] + q[2*GB_KT_STRIDE]
                        + q[3*GB_KT_STRIDE] + bs[16 + g*4 + ucc];
            }
            float ig = sigm(gate[0]), fg = sigm(gate[1]);
            float gg = tanhf(gate[2]), og = sigm(gate[3]);
            c1r = fg*c1r + ig*gg;
            float hn = og * tanhf(c1r);
            g_h1T[1 - p][col][ub] = hn;
            out[(size_t)t*(BSZ*HID) + ub*HID + col] = hn;
        }
        grid_bar();
    }

    // ---- epilogue: (hT, cT); T even -> final states in buffer 0 ----
    {
        const size_t OFF = (size_t)T_LEN * BSZ * HID;
        int li = ub*HID + col;
        out[OFF +             li] = g_h0T[0][col][ub];
        out[OFF +  32768 +    li] = g_h1T[0][col][ub];
        out[OFF +  65536 +    li] = c0r;
        out[OFF +  98304 +    li] = c1r;
    }
}

extern "C" void kernel_launch(void* const* d_in, const int* in_sizes, int n_in,
                              void* d_out, int out_size) {
    const float* x   = (const float*)d_in[0];
    const float* Wxh = (const float*)d_in[1];
    const float* Whh = (const float*)d_in[2];
    const float* bxh = (const float*)d_in[3];
    const float* bhh = (const float*)d_in[4];
    float* out = (float*)d_out;

    transpose_x<<<dim3(16, 2, T_LEN), dim3(32, 8)>>>(x);

    cudaFuncSetAttribute(lstm_persistent,
                         cudaFuncAttributeMaxDynamicSharedMemorySize, SMEM_BYTES);
    lstm_persistent<<<NCTA, NTHR, SMEM_BYTES>>>(Wxh, Whh, bxh, bhh, out);
}